// round 2
// baseline (speedup 1.0000x reference)
#include <cuda_runtime.h>
#include <math.h>

#define BB 2
#define DIMC 96
#define INNER 192
#define NH 48
#define DH 4
#define SS 576
#define GTOT (BB*SS)   // 1152

// Scratch (device globals; no allocation allowed)
__device__ float g_xi[GTOT * 2 * INNER];   // up-proj output (x_mlstm | z)
__device__ float g_xconv[GTOT * INNER];    // silu(causal conv)
__device__ float g_qkv[GTOT * 3 * INNER];  // [q | k | v] per position
__device__ float g_ig[BB * NH * SS];
__device__ float g_fg[BB * NH * SS];
__device__ float g_hnorm[GTOT * INNER];

// ---------------------------------------------------------------------------
// K1: LayerNorm over C=96 + up-projection to 384. 16 positions per block.
// ---------------------------------------------------------------------------
__global__ void k1_ln_up(const float* __restrict__ x,
                         const float* __restrict__ ln_g,
                         const float* __restrict__ ln_b,
                         const float* __restrict__ w_up,
                         const float* __restrict__ b_up) {
    __shared__ float h[16][DIMC];
    __shared__ float mu[16], iv[16];
    const int g0 = blockIdx.x * 16;            // global position base (b*S+s)
    const int b = g0 / SS, s0 = g0 % SS;       // blocks never cross batch (576%16==0)
    const int tid = threadIdx.x;               // 384 threads

    for (int i = tid; i < 16 * DIMC; i += 384) {
        int c = i >> 4, p = i & 15;
        h[p][c] = x[(b * DIMC + c) * SS + s0 + p];
    }
    __syncthreads();
    if (tid < 16) {
        float sum = 0.f, sq = 0.f;
        for (int c = 0; c < DIMC; c++) { float v = h[tid][c]; sum += v; sq += v * v; }
        float m = sum * (1.f / DIMC);
        float var = sq * (1.f / DIMC) - m * m;
        mu[tid] = m;
        iv[tid] = rsqrtf(var + 1e-5f);
    }
    __syncthreads();
    for (int i = tid; i < 16 * DIMC; i += 384) {
        int c = i >> 4, p = i & 15;
        h[p][c] = (h[p][c] - mu[p]) * iv[p] * ln_g[c] + ln_b[c];
    }
    __syncthreads();

    const int o = tid;   // 384 outputs exactly
    float acc[16];
    float bias = b_up[o];
#pragma unroll
    for (int p = 0; p < 16; p++) acc[p] = bias;
    for (int c = 0; c < DIMC; c++) {
        float w = w_up[o * DIMC + c];
#pragma unroll
        for (int p = 0; p < 16; p++) acc[p] += w * h[p][c];
    }
#pragma unroll
    for (int p = 0; p < 16; p++) g_xi[(g0 + p) * (2 * INNER) + o] = acc[p];
}

// ---------------------------------------------------------------------------
// K2: causal depthwise conv (K=4) + SiLU on x_mlstm (= g_xi[..., :192])
// ---------------------------------------------------------------------------
__global__ void k2_conv(const float* __restrict__ w_conv,
                        const float* __restrict__ b_conv) {
    int t = blockIdx.x * 256 + threadIdx.x;
    if (t >= GTOT * INNER) return;
    int d = t % INNER;
    int g = t / INNER;
    int s = g % SS;
    float acc = b_conv[d];
#pragma unroll
    for (int k = 0; k < 4; k++) {
        int sp = s - 3 + k;
        if (sp >= 0) acc += w_conv[d * 4 + k] * g_xi[(g - 3 + k) * (2 * INNER) + d];
    }
    float sg = 1.f / (1.f + __expf(-acc));
    g_xconv[t] = acc * sg;
}

// ---------------------------------------------------------------------------
// K3: per-head 4x4 block-diagonal q/k/v; q,k from x_conv, v from x_mlstm
// ---------------------------------------------------------------------------
__global__ void k3_qkv(const float* __restrict__ w_q, const float* __restrict__ b_q,
                       const float* __restrict__ w_k, const float* __restrict__ b_k,
                       const float* __restrict__ w_v, const float* __restrict__ b_v) {
    int t = blockIdx.x * 256 + threadIdx.x;
    if (t >= GTOT * NH) return;
    int n = t % NH;
    int g = t / NH;
    float4 xc = *(const float4*)(g_xconv + g * INNER + n * 4);
    float4 xm = *(const float4*)(g_xi + g * (2 * INNER) + n * 4);
    float q[4], k[4], v[4];
#pragma unroll
    for (int o = 0; o < 4; o++) {
        const float* wq = w_q + n * 16 + o * 4;
        q[o] = b_q[n * 4 + o] + wq[0] * xc.x + wq[1] * xc.y + wq[2] * xc.z + wq[3] * xc.w;
        const float* wk = w_k + n * 16 + o * 4;
        k[o] = b_k[n * 4 + o] + wk[0] * xc.x + wk[1] * xc.y + wk[2] * xc.z + wk[3] * xc.w;
        const float* wv = w_v + n * 16 + o * 4;
        v[o] = b_v[n * 4 + o] + wv[0] * xm.x + wv[1] * xm.y + wv[2] * xm.z + wv[3] * xm.w;
    }
    float* out = g_qkv + g * (3 * INNER);
    *(float4*)(out + n * 4)             = make_float4(q[0], q[1], q[2], q[3]);
    *(float4*)(out + INNER + n * 4)     = make_float4(k[0], k[1], k[2], k[3]);
    *(float4*)(out + 2 * INNER + n * 4) = make_float4(v[0], v[1], v[2], v[3]);
}

// ---------------------------------------------------------------------------
// K3b: input/forget gate pre-activations: ig/fg[b,n,s] = qkv[b,s]·w[n] + bias
// 8 positions per block, 96 threads (48 ig rows + 48 fg rows)
// ---------------------------------------------------------------------------
__global__ void k3b_gates(const float* __restrict__ w_ig, const float* __restrict__ b_ig,
                          const float* __restrict__ w_fg, const float* __restrict__ b_fg) {
    __shared__ float sq[8 * 3 * INNER];   // 18KB
    const int g0 = blockIdx.x * 8;
    const int tid = threadIdx.x;          // 96
    for (int i = tid; i < 8 * 3 * INNER; i += 96)
        sq[i] = g_qkv[g0 * (3 * INNER) + i];
    __syncthreads();

    const bool isig = tid < NH;
    const int n = tid % NH;
    const float* wrow = (isig ? w_ig : w_fg) + n * (3 * INNER);
    float bias = isig ? b_ig[n] : b_fg[n];
    float acc[8];
#pragma unroll
    for (int p = 0; p < 8; p++) acc[p] = bias;
    for (int f = 0; f < 3 * INNER; f++) {
        float w = wrow[f];
#pragma unroll
        for (int p = 0; p < 8; p++) acc[p] += w * sq[p * (3 * INNER) + f];
    }
    float* dst = isig ? g_ig : g_fg;
    const int b = g0 / SS, s0 = g0 % SS;
#pragma unroll
    for (int p = 0; p < 8; p++) dst[(b * NH + n) * SS + s0 + p] = acc[p];
}

// ---------------------------------------------------------------------------
// K4: mLSTM parallel form + fused MultiHeadLayerNorm.
// One block per (b,head); thread s = output row.
//   a[t]   = ig[t] - lf_cum[t+1]
//   Dm[s,t]= exp(a[t] - M[s]),  M[s] = max_{t<=s} a[t]
//   norm   = max(|sum_t qk*Dm|, exp(-(lf_cum[s+1]+M[s])))
// ---------------------------------------------------------------------------
__global__ void k4_mlstm(const float* __restrict__ on_g,
                         const float* __restrict__ on_b) {
    __shared__ float sbuf[SS];
    __shared__ float a_s[SS];
    __shared__ float4 kk[SS];
    __shared__ float4 vv[SS];
    const int bh = blockIdx.x;
    const int b = bh / NH, n = bh % NH;
    const int s = threadIdx.x;

    float fgv = g_fg[bh * SS + s];
    float igv = g_ig[bh * SS + s];
    // log_sigmoid, numerically stable
    float logf = (fgv > 0.f) ? -log1pf(__expf(-fgv)) : (fgv - log1pf(__expf(fgv)));
    sbuf[s] = logf;
    __syncthreads();
    // inclusive prefix sum (Hillis-Steele) -> lf_cum[s+1]
    for (int off = 1; off < SS; off <<= 1) {
        float v = sbuf[s];
        float add = (s >= off) ? sbuf[s - off] : 0.f;
        __syncthreads();
        sbuf[s] = v + add;
        __syncthreads();
    }
    const float cums = sbuf[s];
    const float a = igv - cums;
    a_s[s] = a;

    const float* row = g_qkv + (b * SS + s) * (3 * INNER) + n * 4;
    const float4 q4 = *(const float4*)(row);
    kk[s] = *(const float4*)(row + INNER);
    vv[s] = *(const float4*)(row + 2 * INNER);
    __syncthreads();

    // running max of a over t<=s (2-way ILP)
    float M0 = -1e30f, M1 = -1e30f;
    int t = 0;
    for (; t + 1 <= s; t += 2) {
        M0 = fmaxf(M0, a_s[t]);
        M1 = fmaxf(M1, a_s[t + 1]);
    }
    if (t <= s) M0 = fmaxf(M0, a_s[t]);
    const float M = fmaxf(M0, M1);

    float csum = 0.f, o0 = 0.f, o1 = 0.f, o2 = 0.f, o3 = 0.f;
    for (int tt = 0; tt <= s; tt++) {
        float e = __expf(a_s[tt] - M);
        float4 kt = kk[tt];
        float4 vt = vv[tt];
        float qk = (q4.x * kt.x + q4.y * kt.y + q4.z * kt.z + q4.w * kt.w) * 0.5f;
        float c = qk * e;
        csum += c;
        o0 += c * vt.x; o1 += c * vt.y; o2 += c * vt.z; o3 += c * vt.w;
    }
    float norm = fmaxf(fabsf(csum), __expf(-(cums + M)));
    float inv = 1.f / (norm + 1e-6f);
    float h0 = o0 * inv, h1 = o1 * inv, h2 = o2 * inv, h3 = o3 * inv;

    // MultiHeadLayerNorm over DH=4
    float m = (h0 + h1 + h2 + h3) * 0.25f;
    float d0 = h0 - m, d1 = h1 - m, d2 = h2 - m, d3 = h3 - m;
    float var = (d0 * d0 + d1 * d1 + d2 * d2 + d3 * d3) * 0.25f;
    float r = rsqrtf(var + 1e-5f);
    float4 og = *(const float4*)(on_g + n * 4);
    float4 ob = *(const float4*)(on_b + n * 4);
    float4 out = make_float4(d0 * r * og.x + ob.x,
                             d1 * r * og.y + ob.y,
                             d2 * r * og.z + ob.z,
                             d3 * r * og.w + ob.w);
    *(float4*)(g_hnorm + (b * SS + s) * INNER + n * 4) = out;
}

// ---------------------------------------------------------------------------
// K5: h_skip = h_norm + skip*x_conv; h_state = h_skip * silu(z);
//     out = h_state @ w_down^T + b_down; y = xs + out   (written NCHW)
// ---------------------------------------------------------------------------
__global__ void k5_down(const float* __restrict__ x,
                        const float* __restrict__ skip,
                        const float* __restrict__ w_down,
                        const float* __restrict__ b_down,
                        float* __restrict__ out) {
    __shared__ float hs[16 * INNER];   // 12KB
    const int g0 = blockIdx.x * 16;
    const int tid = threadIdx.x;       // 96
    for (int i = tid; i < 16 * INNER; i += 96) {
        int p = i / INNER, d = i % INNER;
        int g = g0 + p;
        float hn = g_hnorm[g * INNER + d];
        float xc = g_xconv[g * INNER + d];
        float z = g_xi[g * (2 * INNER) + INNER + d];
        float sg = 1.f / (1.f + __expf(-z));
        hs[i] = (hn + skip[d] * xc) * (z * sg);
    }
    __syncthreads();

    const int c = tid;   // 96 output channels
    float acc[16];
#pragma unroll
    for (int p = 0; p < 16; p++) acc[p] = b_down[c];
    for (int f = 0; f < INNER; f++) {
        float w = w_down[c * INNER + f];
#pragma unroll
        for (int p = 0; p < 16; p++) acc[p] += w * hs[p * INNER + f];
    }
    const int b = g0 / SS, s0 = g0 % SS;
#pragma unroll
    for (int p = 0; p < 16; p++) {
        int idx = (b * DIMC + c) * SS + s0 + p;
        out[idx] = x[idx] + acc[p];
    }
}

// ---------------------------------------------------------------------------
extern "C" void kernel_launch(void* const* d_in, const int* in_sizes, int n_in,
                              void* d_out, int out_size) {
    const float* x      = (const float*)d_in[0];
    const float* ln_g   = (const float*)d_in[1];
    const float* ln_b   = (const float*)d_in[2];
    const float* w_up   = (const float*)d_in[3];
    const float* b_up   = (const float*)d_in[4];
    const float* w_q    = (const float*)d_in[5];
    const float* b_q    = (const float*)d_in[6];
    const float* w_k    = (const float*)d_in[7];
    const float* b_k    = (const float*)d_in[8];
    const float* w_v    = (const float*)d_in[9];
    const float* b_v    = (const float*)d_in[10];
    const float* w_conv = (const float*)d_in[11];
    const float* b_conv = (const float*)d_in[12];
    const float* w_ig   = (const float*)d_in[13];
    const float* b_ig   = (const float*)d_in[14];
    const float* w_fg   = (const float*)d_in[15];
    const float* b_fg   = (const float*)d_in[16];
    const float* on_g   = (const float*)d_in[17];
    const float* on_b   = (const float*)d_in[18];
    const float* skip   = (const float*)d_in[19];
    const float* w_down = (const float*)d_in[20];
    const float* b_down = (const float*)d_in[21];
    float* out = (float*)d_out;

    k1_ln_up<<<GTOT / 16, 384>>>(x, ln_g, ln_b, w_up, b_up);
    k2_conv<<<(GTOT * INNER + 255) / 256, 256>>>(w_conv, b_conv);
    k3_qkv<<<(GTOT * NH + 255) / 256, 256>>>(w_q, b_q, w_k, b_k, w_v, b_v);
    k3b_gates<<<GTOT / 8, 96>>>(w_ig, b_ig, w_fg, b_fg);
    k4_mlstm<<<BB * NH, SS>>>(on_g, on_b);
    k5_down<<<GTOT / 16, 96>>>(x, skip, w_down, b_down, out);
}

// round 3
// speedup vs baseline: 1.3707x; 1.3707x over previous
#include <cuda_runtime.h>
#include <math.h>

#define BB 2
#define DIMC 96
#define INNER 192
#define NH 48
#define DH 4
#define SS 576
#define GTOT (BB*SS)   // 1152
#define F3 (3*INNER)   // 576

// Scratch (device globals; no allocation allowed)
__device__ float g_xi[GTOT * 2 * INNER];   // up-proj output (x_mlstm | z)
__device__ float g_xconv[GTOT * INNER];    // silu(causal conv)
__device__ float g_qkv[GTOT * 3 * INNER];  // [q | k | v] per position
__device__ float g_ig[BB * NH * SS];
__device__ float g_fg[BB * NH * SS];
__device__ float g_hnorm[GTOT * INNER];

// ---------------------------------------------------------------------------
// K1: LayerNorm over C=96 + up-projection to 384. 8 positions per block,
// 384 threads, 144 blocks (one per SM on B200).
// ---------------------------------------------------------------------------
__global__ void k1_ln_up(const float* __restrict__ x,
                         const float* __restrict__ ln_g,
                         const float* __restrict__ ln_b,
                         const float* __restrict__ w_up,
                         const float* __restrict__ b_up) {
    __shared__ float h[8][DIMC];
    __shared__ float mu[8], iv[8];
    const int g0 = blockIdx.x * 8;
    const int b = g0 / SS, s0 = g0 % SS;
    const int tid = threadIdx.x;               // 384 threads

    for (int i = tid; i < 8 * DIMC; i += 384) {
        int c = i >> 3, p = i & 7;
        h[p][c] = x[(b * DIMC + c) * SS + s0 + p];
    }
    __syncthreads();
    // warp-per-position stats (first 8 warps)
    if (tid < 256) {
        int p = tid >> 5, lane = tid & 31;
        float sum = 0.f, sq = 0.f;
        for (int c = lane; c < DIMC; c += 32) { float v = h[p][c]; sum += v; sq += v * v; }
#pragma unroll
        for (int off = 16; off > 0; off >>= 1) {
            sum += __shfl_down_sync(0xffffffffu, sum, off);
            sq  += __shfl_down_sync(0xffffffffu, sq, off);
        }
        if (lane == 0) {
            float m = sum * (1.f / DIMC);
            float var = sq * (1.f / DIMC) - m * m;
            mu[p] = m;
            iv[p] = rsqrtf(var + 1e-5f);
        }
    }
    __syncthreads();
    for (int i = tid; i < 8 * DIMC; i += 384) {
        int c = i >> 3, p = i & 7;
        h[p][c] = (h[p][c] - mu[p]) * iv[p] * ln_g[c] + ln_b[c];
    }
    __syncthreads();

    const int o = tid;   // 384 outputs exactly
    float acc[8];
    float bias = b_up[o];
#pragma unroll
    for (int p = 0; p < 8; p++) acc[p] = bias;
    for (int c = 0; c < DIMC; c++) {
        float w = w_up[o * DIMC + c];
#pragma unroll
        for (int p = 0; p < 8; p++) acc[p] += w * h[p][c];
    }
#pragma unroll
    for (int p = 0; p < 8; p++) g_xi[(g0 + p) * (2 * INNER) + o] = acc[p];
}

// ---------------------------------------------------------------------------
// K23: fused causal depthwise conv (K=4) + SiLU + per-head 4x4 q/k/v
// one thread per (position, head)
// ---------------------------------------------------------------------------
__global__ void k23_conv_qkv(const float* __restrict__ w_conv,
                             const float* __restrict__ b_conv,
                             const float* __restrict__ w_q, const float* __restrict__ b_q,
                             const float* __restrict__ w_k, const float* __restrict__ b_k,
                             const float* __restrict__ w_v, const float* __restrict__ b_v) {
    int t = blockIdx.x * 256 + threadIdx.x;
    if (t >= GTOT * NH) return;
    int n = t % NH;
    int g = t / NH;
    int s = g % SS;

    // conv over channels d = 4n..4n+3
    float xc[4];
    float4 xm = make_float4(0.f, 0.f, 0.f, 0.f);
#pragma unroll
    for (int d = 0; d < 4; d++) xc[d] = b_conv[n * 4 + d];
#pragma unroll
    for (int k = 0; k < 4; k++) {
        int sp = s - 3 + k;
        if (sp >= 0) {
            float4 xk = *(const float4*)(g_xi + (g - 3 + k) * (2 * INNER) + n * 4);
            if (k == 3) xm = xk;
#pragma unroll
            for (int d = 0; d < 4; d++)
                xc[d] += w_conv[(n * 4 + d) * 4 + k] * ((const float*)&xk)[d];
        }
    }
#pragma unroll
    for (int d = 0; d < 4; d++) {
        float sg = 1.f / (1.f + __expf(-xc[d]));
        xc[d] *= sg;
    }
    *(float4*)(g_xconv + g * INNER + n * 4) = make_float4(xc[0], xc[1], xc[2], xc[3]);

    float q[4], k4_[4], v[4];
#pragma unroll
    for (int o = 0; o < 4; o++) {
        const float* wq = w_q + n * 16 + o * 4;
        q[o] = b_q[n * 4 + o] + wq[0] * xc[0] + wq[1] * xc[1] + wq[2] * xc[2] + wq[3] * xc[3];
        const float* wk = w_k + n * 16 + o * 4;
        k4_[o] = b_k[n * 4 + o] + wk[0] * xc[0] + wk[1] * xc[1] + wk[2] * xc[2] + wk[3] * xc[3];
        const float* wv = w_v + n * 16 + o * 4;
        v[o] = b_v[n * 4 + o] + wv[0] * xm.x + wv[1] * xm.y + wv[2] * xm.z + wv[3] * xm.w;
    }
    float* out = g_qkv + g * F3;
    *(float4*)(out + n * 4)             = make_float4(q[0], q[1], q[2], q[3]);
    *(float4*)(out + INNER + n * 4)     = make_float4(k4_[0], k4_[1], k4_[2], k4_[3]);
    *(float4*)(out + 2 * INNER + n * 4) = make_float4(v[0], v[1], v[2], v[3]);
}

// ---------------------------------------------------------------------------
// K3b v2: gate pre-activations with split-K.
// 8 positions per block, 384 threads = 96 rows x 4 K-slices (144 each).
// ---------------------------------------------------------------------------
__global__ void k3b_gates(const float* __restrict__ w_ig, const float* __restrict__ b_ig,
                          const float* __restrict__ w_fg, const float* __restrict__ b_fg) {
    __shared__ float sq[8 * F3];           // 18KB
    __shared__ float part[8][4][100];      // [p][slice][row(+pad)] 12.8KB
    const int g0 = blockIdx.x * 8;
    const int tid = threadIdx.x;           // 384
    for (int i = tid; i < 8 * F3; i += 384)
        sq[i] = g_qkv[g0 * F3 + i];
    __syncthreads();

    const int r = tid % 96;
    const int slice = tid / 96;
    const bool isig = r < NH;
    const int n = isig ? r : r - NH;
    const float* wrow = (isig ? w_ig : w_fg) + n * F3 + slice * 144;
    const float* sqs = sq + slice * 144;
    float acc[8];
#pragma unroll
    for (int p = 0; p < 8; p++) acc[p] = 0.f;
    for (int f = 0; f < 144; f++) {
        float w = wrow[f];
#pragma unroll
        for (int p = 0; p < 8; p++) acc[p] += w * sqs[p * F3 + f];
    }
#pragma unroll
    for (int p = 0; p < 8; p++) part[p][slice][r] = acc[p];
    __syncthreads();

    const int b = g0 / SS, s0 = g0 % SS;
#pragma unroll
    for (int j = 0; j < 2; j++) {
        int idx = tid + j * 384;           // 0..767 -> (r2, p2)
        int r2 = idx % 96, p2 = idx / 96;
        float v = part[p2][0][r2] + part[p2][1][r2] + part[p2][2][r2] + part[p2][3][r2];
        bool ii = r2 < NH;
        int n2 = ii ? r2 : r2 - NH;
        v += ii ? b_ig[n2] : b_fg[n2];
        float* dst = ii ? g_ig : g_fg;
        dst[(b * NH + n2) * SS + s0 + p2] = v;
    }
}

// ---------------------------------------------------------------------------
// K4: mLSTM parallel form + fused MultiHeadLayerNorm.
// One block per (b,head); thread s = output row. Warp-shuffle prefix scan.
// ---------------------------------------------------------------------------
__global__ void k4_mlstm(const float* __restrict__ on_g,
                         const float* __restrict__ on_b) {
    __shared__ float a_s[SS];
    __shared__ float4 kk[SS];
    __shared__ float4 vv[SS];
    __shared__ float warpsum[18];
    const int bh = blockIdx.x;
    const int b = bh / NH, n = bh % NH;
    const int s = threadIdx.x;
    const int wid = s >> 5, lane = s & 31;

    float fgv = g_fg[bh * SS + s];
    float igv = g_ig[bh * SS + s];
    float logf = (fgv > 0.f) ? -log1pf(__expf(-fgv)) : (fgv - log1pf(__expf(fgv)));

    // warp inclusive scan
    float v = logf;
#pragma unroll
    for (int off = 1; off < 32; off <<= 1) {
        float nn = __shfl_up_sync(0xffffffffu, v, off);
        if (lane >= off) v += nn;
    }
    if (lane == 31) warpsum[wid] = v;
    __syncthreads();
    if (s == 0) {
        float acc = 0.f;
#pragma unroll
        for (int w = 0; w < 18; w++) { acc += warpsum[w]; warpsum[w] = acc; }
    }
    __syncthreads();
    const float cums = v + (wid > 0 ? warpsum[wid - 1] : 0.f);
    const float a = igv - cums;
    a_s[s] = a;

    const float* row = g_qkv + (b * SS + s) * F3 + n * 4;
    const float4 q4 = *(const float4*)(row);
    kk[s] = *(const float4*)(row + INNER);
    vv[s] = *(const float4*)(row + 2 * INNER);
    __syncthreads();

    // running max of a over t<=s
    float M0 = -1e30f, M1 = -1e30f;
    int t = 0;
    for (; t + 1 <= s; t += 2) {
        M0 = fmaxf(M0, a_s[t]);
        M1 = fmaxf(M1, a_s[t + 1]);
    }
    if (t <= s) M0 = fmaxf(M0, a_s[t]);
    const float M = fmaxf(M0, M1);

    float csum = 0.f, o0 = 0.f, o1 = 0.f, o2 = 0.f, o3 = 0.f;
    for (int tt = 0; tt <= s; tt++) {
        float e = __expf(a_s[tt] - M);
        float4 kt = kk[tt];
        float4 vt = vv[tt];
        float qk = (q4.x * kt.x + q4.y * kt.y + q4.z * kt.z + q4.w * kt.w) * 0.5f;
        float c = qk * e;
        csum += c;
        o0 += c * vt.x; o1 += c * vt.y; o2 += c * vt.z; o3 += c * vt.w;
    }
    float norm = fmaxf(fabsf(csum), __expf(-(cums + M)));
    float inv = 1.f / (norm + 1e-6f);
    float h0 = o0 * inv, h1 = o1 * inv, h2 = o2 * inv, h3 = o3 * inv;

    // MultiHeadLayerNorm over DH=4
    float m = (h0 + h1 + h2 + h3) * 0.25f;
    float d0 = h0 - m, d1 = h1 - m, d2 = h2 - m, d3 = h3 - m;
    float var = (d0 * d0 + d1 * d1 + d2 * d2 + d3 * d3) * 0.25f;
    float r = rsqrtf(var + 1e-5f);
    float4 og = *(const float4*)(on_g + n * 4);
    float4 ob = *(const float4*)(on_b + n * 4);
    float4 out = make_float4(d0 * r * og.x + ob.x,
                             d1 * r * og.y + ob.y,
                             d2 * r * og.z + ob.z,
                             d3 * r * og.w + ob.w);
    *(float4*)(g_hnorm + (b * SS + s) * INNER + n * 4) = out;
}

// ---------------------------------------------------------------------------
// K5 v2: skip + z-gate + down-proj + residual, split-K.
// 8 positions per block, 384 threads = 96 channels x 4 f-slices (48 each).
// ---------------------------------------------------------------------------
__global__ void k5_down(const float* __restrict__ x,
                        const float* __restrict__ skip,
                        const float* __restrict__ w_down,
                        const float* __restrict__ b_down,
                        float* __restrict__ out) {
    __shared__ float hs[8 * INNER];        // 6KB
    __shared__ float part[8][4][100];      // 12.8KB
    const int g0 = blockIdx.x * 8;
    const int tid = threadIdx.x;           // 384
    for (int i = tid; i < 8 * INNER; i += 384) {
        int p = i / INNER, d = i % INNER;
        int g = g0 + p;
        float hn = g_hnorm[g * INNER + d];
        float xc = g_xconv[g * INNER + d];
        float z = g_xi[g * (2 * INNER) + INNER + d];
        float sg = 1.f / (1.f + __expf(-z));
        hs[i] = (hn + skip[d] * xc) * (z * sg);
    }
    __syncthreads();

    const int c = tid % 96;
    const int slice = tid / 96;
    const float* wrow = w_down + c * INNER + slice * 48;
    const float* hss = hs + slice * 48;
    float acc[8];
#pragma unroll
    for (int p = 0; p < 8; p++) acc[p] = 0.f;
    for (int f = 0; f < 48; f++) {
        float w = wrow[f];
#pragma unroll
        for (int p = 0; p < 8; p++) acc[p] += w * hss[p * INNER + f];
    }
#pragma unroll
    for (int p = 0; p < 8; p++) part[p][slice][c] = acc[p];
    __syncthreads();

    const int b = g0 / SS, s0 = g0 % SS;
#pragma unroll
    for (int j = 0; j < 2; j++) {
        int idx = tid + j * 384;           // 0..767
        int c2 = idx % 96, p2 = idx / 96;
        float v = part[p2][0][c2] + part[p2][1][c2] + part[p2][2][c2] + part[p2][3][c2]
                + b_down[c2];
        int gi = (b * DIMC + c2) * SS + s0 + p2;
        out[gi] = x[gi] + v;
    }
}

// ---------------------------------------------------------------------------
extern "C" void kernel_launch(void* const* d_in, const int* in_sizes, int n_in,
                              void* d_out, int out_size) {
    const float* x      = (const float*)d_in[0];
    const float* ln_g   = (const float*)d_in[1];
    const float* ln_b   = (const float*)d_in[2];
    const float* w_up   = (const float*)d_in[3];
    const float* b_up   = (const float*)d_in[4];
    const float* w_q    = (const float*)d_in[5];
    const float* b_q    = (const float*)d_in[6];
    const float* w_k    = (const float*)d_in[7];
    const float* b_k    = (const float*)d_in[8];
    const float* w_v    = (const float*)d_in[9];
    const float* b_v    = (const float*)d_in[10];
    const float* w_conv = (const float*)d_in[11];
    const float* b_conv = (const float*)d_in[12];
    const float* w_ig   = (const float*)d_in[13];
    const float* b_ig   = (const float*)d_in[14];
    const float* w_fg   = (const float*)d_in[15];
    const float* b_fg   = (const float*)d_in[16];
    const float* on_g   = (const float*)d_in[17];
    const float* on_b   = (const float*)d_in[18];
    const float* skip   = (const float*)d_in[19];
    const float* w_down = (const float*)d_in[20];
    const float* b_down = (const float*)d_in[21];
    float* out = (float*)d_out;

    k1_ln_up<<<GTOT / 8, 384>>>(x, ln_g, ln_b, w_up, b_up);
    k23_conv_qkv<<<(GTOT * NH + 255) / 256, 256>>>(w_conv, b_conv,
                                                   w_q, b_q, w_k, b_k, w_v, b_v);
    k3b_gates<<<GTOT / 8, 384>>>(w_ig, b_ig, w_fg, b_fg);
    k4_mlstm<<<BB * NH, SS>>>(on_g, on_b);
    k5_down<<<GTOT / 8, 384>>>(x, skip, w_down, b_down, out);
}